// round 1
// baseline (speedup 1.0000x reference)
#include <cuda_runtime.h>
#include <cstdint>
#include <math.h>

// Problem constants
#define BB   1024
#define LL   2048
#define DEC  64
#define HH   128
#define GG   512      // 4*H gates
#define EIN  18       // input feature size (16 emb + cont*w + x)
#define KK   146      // EIN + HH
#define BT   8        // batch rows per CTA
#define NCTA (BB/BT)  // 128
#define NTHR 256
#define SG   320      // gate columns cached in smem (rest streamed from L2)

// ---------------- persistent device scratch (no allocations allowed) ----------------
__device__ float g_WTe[KK * GG];                    // [k][gate] transposed enc weights
__device__ float g_WTd[KK * GG];                    // dec weights
__device__ float g_fe[(size_t)BB * LL * EIN];       // encoder input features, 151MB
__device__ float g_fd[BB * DEC * 17];               // decoder features (emb+cont*w)

// ---------------- fast activations (MUFU based, ~1e-7 rel err) ----------------
__device__ __forceinline__ float sigf(float x) {
    return __fdividef(1.0f, 1.0f + __expf(-x));
}
__device__ __forceinline__ float tanh_f(float x) {
    float e = __expf(-2.0f * fabsf(x));
    float t = (1.0f - e) * __fdividef(1.0f, 1.0f + e);
    return copysignf(t, x);
}

// ---------------- prep kernels ----------------
__global__ void prep_weights(const float* __restrict__ Wih,
                             const float* __restrict__ Whh,
                             float* __restrict__ WT) {
    int idx = blockIdx.x * blockDim.x + threadIdx.x;   // over KK*GG
    if (idx >= KK * GG) return;
    int k = idx / GG, g = idx - k * GG;
    WT[idx] = (k < EIN) ? Wih[g * EIN + k] : Whh[g * HH + (k - EIN)];
}

__global__ void prep_fe(const int* __restrict__ cat, const float* __restrict__ cont,
                        const float* __restrict__ X, const float* __restrict__ emb,
                        const float* __restrict__ cw, float* __restrict__ out) {
    size_t idx = (size_t)blockIdx.x * blockDim.x + threadIdx.x;  // over BB*LL*EIN
    if (idx >= (size_t)BB * LL * EIN) return;
    size_t bl = idx / EIN;
    int j = (int)(idx - bl * EIN);
    float v;
    if (j < 16)       v = emb[cat[bl] * 16 + j];
    else if (j == 16) v = cont[bl] * cw[0];
    else              v = X[bl];
    out[idx] = v;
}

__global__ void prep_fd(const int* __restrict__ cat, const float* __restrict__ cont,
                        const float* __restrict__ emb, const float* __restrict__ cw,
                        float* __restrict__ out) {
    int idx = blockIdx.x * blockDim.x + threadIdx.x;   // over BB*DEC*17
    if (idx >= BB * DEC * 17) return;
    int bl = idx / 17, j = idx - bl * 17;
    out[idx] = (j < 16) ? emb[cat[bl] * 16 + j] : cont[bl] * cw[0];
}

// ---------------- main persistent LSTM kernel ----------------
template <bool INSM>
__device__ __forceinline__ void mm_loop(const float* __restrict__ ws,
                                        const float* __restrict__ gwt,
                                        const float* __restrict__ xh,
                                        int t0, float* a0, float* a1) {
    const float* w0p = ws + t0;
    const float* w1s = ws + t0 + 256;
    const float* w1g = gwt + t0 + 256;
#pragma unroll 4
    for (int k = 0; k < KK; ++k) {
        float w0 = w0p[k * SG];
        float w1 = INSM ? w1s[k * SG] : __ldcg(w1g + k * GG);
        float4 xa = *reinterpret_cast<const float4*>(xh + k * BT);
        float4 xb = *reinterpret_cast<const float4*>(xh + k * BT + 4);
        a0[0] = fmaf(w0, xa.x, a0[0]);  a0[1] = fmaf(w0, xa.y, a0[1]);
        a0[2] = fmaf(w0, xa.z, a0[2]);  a0[3] = fmaf(w0, xa.w, a0[3]);
        a0[4] = fmaf(w0, xb.x, a0[4]);  a0[5] = fmaf(w0, xb.y, a0[5]);
        a0[6] = fmaf(w0, xb.z, a0[6]);  a0[7] = fmaf(w0, xb.w, a0[7]);
        a1[0] = fmaf(w1, xa.x, a1[0]);  a1[1] = fmaf(w1, xa.y, a1[1]);
        a1[2] = fmaf(w1, xa.z, a1[2]);  a1[3] = fmaf(w1, xa.w, a1[3]);
        a1[4] = fmaf(w1, xb.x, a1[4]);  a1[5] = fmaf(w1, xb.y, a1[5]);
        a1[6] = fmaf(w1, xb.z, a1[6]);  a1[7] = fmaf(w1, xb.w, a1[7]);
    }
}

__device__ __forceinline__ void do_matmul(const float* __restrict__ ws,
                                          const float* __restrict__ gwt,
                                          const float* __restrict__ xh,
                                          float* __restrict__ gates,
                                          int t0, float b0v, float b1v) {
    float a0[8], a1[8];
#pragma unroll
    for (int r = 0; r < 8; ++r) { a0[r] = b0v; a1[r] = b1v; }
    if (t0 < 64) mm_loop<true>(ws, gwt, xh, t0, a0, a1);
    else         mm_loop<false>(ws, gwt, xh, t0, a0, a1);
    float4* gp0 = reinterpret_cast<float4*>(gates + t0 * BT);
    gp0[0] = make_float4(a0[0], a0[1], a0[2], a0[3]);
    gp0[1] = make_float4(a0[4], a0[5], a0[6], a0[7]);
    float4* gp1 = reinterpret_cast<float4*>(gates + (t0 + 256) * BT);
    gp1[0] = make_float4(a1[0], a1[1], a1[2], a1[3]);
    gp1[1] = make_float4(a1[4], a1[5], a1[6], a1[7]);
}

__device__ __forceinline__ void ld8(const float* __restrict__ p, float* v) {
    float4 a = *reinterpret_cast<const float4*>(p);
    float4 b = *reinterpret_cast<const float4*>(p + 4);
    v[0] = a.x; v[1] = a.y; v[2] = a.z; v[3] = a.w;
    v[4] = b.x; v[5] = b.y; v[6] = b.z; v[7] = b.w;
}

__device__ __forceinline__ void cell_update(const float* __restrict__ gates,
                                            float* __restrict__ xh, int j, float* c) {
    float iv[8], fv[8], gv[8], ov[8];
    ld8(gates + j * BT, iv);
    ld8(gates + (128 + j) * BT, fv);
    ld8(gates + (256 + j) * BT, gv);
    ld8(gates + (384 + j) * BT, ov);
    float hv[8];
#pragma unroll
    for (int r = 0; r < 8; ++r) {
        float cn = sigf(fv[r]) * c[r] + sigf(iv[r]) * tanh_f(gv[r]);
        c[r] = cn;
        hv[r] = sigf(ov[r]) * tanh_f(cn);
    }
    float4* hp = reinterpret_cast<float4*>(xh + (EIN + j) * BT);
    hp[0] = make_float4(hv[0], hv[1], hv[2], hv[3]);
    hp[1] = make_float4(hv[4], hv[5], hv[6], hv[7]);
}

__global__ void __launch_bounds__(NTHR, 1)
model_kernel(const float* __restrict__ b_e, const float* __restrict__ b_d,
             const float* __restrict__ Wm, const float* __restrict__ bm,
             const float* __restrict__ Wsw, const float* __restrict__ bs,
             const float* __restrict__ Wv, const float* __restrict__ bv,
             float* __restrict__ out) {
    extern __shared__ float sm[];
    float* ws    = sm;                   // KK*SG
    float* xh    = ws + KK * SG;         // KK*BT : [x(18) | h(128)] x 8 rows
    float* gates = xh + KK * BT;         // GG*BT
    float* hw    = gates + GG * BT;      // 768 head weights + 6 biases

    int tid = threadIdx.x;
    int b0r = blockIdx.x * BT;

    // load encoder weights into smem
    for (int i = tid; i < KK * SG; i += NTHR) {
        int k = i / SG, g = i - k * SG;
        ws[i] = g_WTe[k * GG + g];
    }
    for (int i = tid; i < KK * BT; i += NTHR) xh[i] = 0.0f;
    if (tid < BT * EIN) {
        int r = tid / EIN, k = tid - r * EIN;
        xh[k * BT + r] = g_fe[(size_t)(b0r + r) * LL * EIN + k];
    }
    if (tid < 128) {
        hw[tid]       = Wm[tid];
        hw[128 + tid] = Wsw[tid];
#pragma unroll
        for (int d = 0; d < 4; ++d) hw[256 + d * 128 + tid] = Wv[d * 128 + tid];
    }
    if (tid == 0) {
        hw[768] = bm[0]; hw[769] = bs[0];
        hw[770] = bv[0]; hw[771] = bv[1]; hw[772] = bv[2]; hw[773] = bv[3];
    }

    float c[8];
#pragma unroll
    for (int r = 0; r < 8; ++r) c[r] = 0.0f;
    float be0 = b_e[tid], be1 = b_e[tid + 256];

    // ---------------- encoder: 2048 steps ----------------
#pragma unroll 1
    for (int t = 0; t < LL; ++t) {
        __syncthreads();                       // xh complete
        do_matmul(ws, g_WTe, xh, gates, tid, be0, be1);
        // prefetch next step's input features
        float pf = 0.0f;
        bool havepf = (tid < BT * EIN) && (t + 1 < LL);
        int pr = tid / EIN, pk = tid - pr * EIN;
        if (havepf)
            pf = g_fe[(size_t)(b0r + pr) * LL * EIN + (size_t)(t + 1) * EIN + pk];
        __syncthreads();                       // gates complete
        if (tid < HH) cell_update(gates, xh, tid, c);
        if (havepf) xh[pk * BT + pr] = pf;
    }
    // after loop: xh x-part still holds t=2047 features = decoder-t0 input
    // (f_prev = feats_in_embed[:, -1], x_prev = X_in[:, -1])

    __syncthreads();
    // swap to decoder weights
    for (int i = tid; i < KK * SG; i += NTHR) {
        int k = i / SG, g = i - k * SG;
        ws[i] = g_WTd[k * GG + g];
    }
    float bd0 = b_d[tid], bd1 = b_d[tid + 256];
    int lane = tid & 31, wrp = tid >> 5;

    // ---------------- decoder: 64 autoregressive steps ----------------
#pragma unroll 1
    for (int t = 0; t < DEC; ++t) {
        __syncthreads();
        do_matmul(ws, g_WTd, xh, gates, tid, bd0, bd1);
        float pf = 0.0f;
        bool havepf = (tid < BT * 17) && (t < DEC - 1);
        int pr = tid / 17, pk = tid - pr * 17;
        if (havepf)
            pf = g_fd[((b0r + pr) * DEC + t) * 17 + pk];
        __syncthreads();
        if (tid < HH) cell_update(gates, xh, tid, c);
        __syncthreads();                       // h complete for heads
        {
            int r = wrp;  // 8 warps -> 8 batch rows
            float hm = 0.f, hs = 0.f, hv0 = 0.f, hv1 = 0.f, hv2 = 0.f, hv3 = 0.f;
#pragma unroll
            for (int q = 0; q < 4; ++q) {
                int j = lane + q * 32;
                float h = xh[(EIN + j) * BT + r];
                hm  = fmaf(h, hw[j], hm);
                hs  = fmaf(h, hw[128 + j], hs);
                hv0 = fmaf(h, hw[256 + j], hv0);
                hv1 = fmaf(h, hw[384 + j], hv1);
                hv2 = fmaf(h, hw[512 + j], hv2);
                hv3 = fmaf(h, hw[640 + j], hv3);
            }
#pragma unroll
            for (int off = 16; off; off >>= 1) {
                hm  += __shfl_xor_sync(0xffffffffu, hm,  off);
                hs  += __shfl_xor_sync(0xffffffffu, hs,  off);
                hv0 += __shfl_xor_sync(0xffffffffu, hv0, off);
                hv1 += __shfl_xor_sync(0xffffffffu, hv1, off);
                hv2 += __shfl_xor_sync(0xffffffffu, hv2, off);
                hv3 += __shfl_xor_sync(0xffffffffu, hv3, off);
            }
            if (lane == 0) {
                float mu = hm + hw[768];
                float sp = hs + hw[769];
                float stdv = fmaxf(sp, 0.0f) + log1pf(__expf(-fabsf(sp)));
                int b = b0r + r;
                out[b * DEC + t] = mu;
                out[BB * DEC + b * DEC + t] = stdv;
                float* vo = out + 2 * BB * DEC + (b * DEC + t) * 4;
                vo[0] = hv0 + hw[770]; vo[1] = hv1 + hw[771];
                vo[2] = hv2 + hw[772]; vo[3] = hv3 + hw[773];
                xh[17 * BT + r] = mu;   // mu feedback -> x_prev
            }
        }
        if (havepf) xh[pk * BT + pr] = pf;   // f_prev <- feats_out_embed[t]
    }
}

// ---------------- launch ----------------
extern "C" void kernel_launch(void* const* d_in, const int* in_sizes, int n_in,
                              void* d_out, int out_size) {
    const int*   cat_in   = (const int*)d_in[0];
    const float* cont_in  = (const float*)d_in[1];
    const float* X_in     = (const float*)d_in[2];
    const int*   cat_out  = (const int*)d_in[3];
    const float* cont_out = (const float*)d_in[4];
    const float* emb      = (const float*)d_in[5];
    const float* cw       = (const float*)d_in[6];
    const float* Wih_e    = (const float*)d_in[7];
    const float* Whh_e    = (const float*)d_in[8];
    const float* b_e      = (const float*)d_in[9];
    const float* Wih_d    = (const float*)d_in[10];
    const float* Whh_d    = (const float*)d_in[11];
    const float* b_d      = (const float*)d_in[12];
    const float* Wm       = (const float*)d_in[13];
    const float* bm       = (const float*)d_in[14];
    const float* Ws       = (const float*)d_in[15];
    const float* bs       = (const float*)d_in[16];
    const float* Wv       = (const float*)d_in[17];
    const float* bv       = (const float*)d_in[18];
    float* out = (float*)d_out;

    float *pWTe, *pWTd, *pfe, *pfd;
    cudaGetSymbolAddress((void**)&pWTe, g_WTe);
    cudaGetSymbolAddress((void**)&pWTd, g_WTd);
    cudaGetSymbolAddress((void**)&pfe,  g_fe);
    cudaGetSymbolAddress((void**)&pfd,  g_fd);

    prep_weights<<<(KK * GG + 255) / 256, 256>>>(Wih_e, Whh_e, pWTe);
    prep_weights<<<(KK * GG + 255) / 256, 256>>>(Wih_d, Whh_d, pWTd);
    size_t ne = (size_t)BB * LL * EIN;
    prep_fe<<<(unsigned)((ne + 255) / 256), 256>>>(cat_in, cont_in, X_in, emb, cw, pfe);
    prep_fd<<<(BB * DEC * 17 + 255) / 256, 256>>>(cat_out, cont_out, emb, cw, pfd);

    int smem_bytes = (KK * SG + KK * BT + GG * BT + 774) * (int)sizeof(float);
    cudaFuncSetAttribute(model_kernel, cudaFuncAttributeMaxDynamicSharedMemorySize, smem_bytes);
    model_kernel<<<NCTA, NTHR, smem_bytes>>>(b_e, b_d, Wm, bm, Ws, bs, Wv, bv, out);
}

// round 2
// speedup vs baseline: 2.3233x; 2.3233x over previous
#include <cuda_runtime.h>
#include <cstdint>
#include <math.h>

// Problem constants
#define BB   1024
#define LL   2048
#define DEC  64
#define HH   128
#define GG   512      // 4*H gates
#define EIN  18       // input feature size (16 emb + cont*w + x)
#define KK   146      // EIN + HH
#define BT   8        // batch rows per CTA
#define NCTA (BB/BT)  // 128
#define NTHR 256
#define W0N  256      // gate columns kept in smem; columns 256..511 live in registers

typedef unsigned long long ull;

// ---------------- persistent device scratch ----------------
__device__ float g_WTe[KK * GG];
__device__ float g_WTd[KK * GG];
__device__ float g_fe[(size_t)BB * LL * EIN];
__device__ float g_fd[BB * DEC * 17];

// ---------------- packed fp32x2 helpers (sm_103a) ----------------
__device__ __forceinline__ ull ffma2(ull a, ull b, ull c) {
    ull d;
    asm("fma.rn.f32x2 %0, %1, %2, %3;" : "=l"(d) : "l"(a), "l"(b), "l"(c));
    return d;
}
__device__ __forceinline__ ull pack2(float x) {
    ull d;
    asm("mov.b64 %0, {%1, %2};" : "=l"(d) : "f"(x), "f"(x));
    return d;
}

// ---------------- fast activations (MUFU based, ~1e-7 rel err) ----------------
__device__ __forceinline__ float sigf(float x) {
    return __fdividef(1.0f, 1.0f + __expf(-x));
}
__device__ __forceinline__ float tanh_f(float x) {
    float e = __expf(-2.0f * fabsf(x));
    float t = (1.0f - e) * __fdividef(1.0f, 1.0f + e);
    return copysignf(t, x);
}

// ---------------- prep kernels ----------------
__global__ void prep_weights(const float* __restrict__ Wih,
                             const float* __restrict__ Whh,
                             float* __restrict__ WT) {
    int idx = blockIdx.x * blockDim.x + threadIdx.x;
    if (idx >= KK * GG) return;
    int k = idx / GG, g = idx - k * GG;
    WT[idx] = (k < EIN) ? Wih[g * EIN + k] : Whh[g * HH + (k - EIN)];
}

__global__ void prep_fe(const int* __restrict__ cat, const float* __restrict__ cont,
                        const float* __restrict__ X, const float* __restrict__ emb,
                        const float* __restrict__ cw, float* __restrict__ out) {
    size_t idx = (size_t)blockIdx.x * blockDim.x + threadIdx.x;
    if (idx >= (size_t)BB * LL * EIN) return;
    size_t bl = idx / EIN;
    int j = (int)(idx - bl * EIN);
    float v;
    if (j < 16)       v = emb[cat[bl] * 16 + j];
    else if (j == 16) v = cont[bl] * cw[0];
    else              v = X[bl];
    out[idx] = v;
}

__global__ void prep_fd(const int* __restrict__ cat, const float* __restrict__ cont,
                        const float* __restrict__ emb, const float* __restrict__ cw,
                        float* __restrict__ out) {
    int idx = blockIdx.x * blockDim.x + threadIdx.x;
    if (idx >= BB * DEC * 17) return;
    int bl = idx / 17, j = idx - bl * 17;
    out[idx] = (j < 16) ? emb[cat[bl] * 16 + j] : cont[bl] * cw[0];
}

// ---------------- main persistent LSTM kernel ----------------
__global__ void __launch_bounds__(NTHR, 1)
model_kernel(const float* __restrict__ b_e, const float* __restrict__ b_d,
             const float* __restrict__ Wm, const float* __restrict__ bm,
             const float* __restrict__ Wsw, const float* __restrict__ bs,
             const float* __restrict__ Wv, const float* __restrict__ bv,
             float* __restrict__ out) {
    extern __shared__ float sm[];
    float* ws    = sm;                   // KK*W0N : weight cols [0,256)
    float* xh    = ws + KK * W0N;        // KK*BT  : [x(18) | h(128)] x 8 rows
    float* gates = xh + KK * BT;         // GG*BT
    float* hw    = gates + GG * BT;      // 768 head weights + 6 biases

    int tid = threadIdx.x;
    int b0r = blockIdx.x * BT;

    // encoder weights: smem half
    for (int i = tid; i < KK * W0N; i += NTHR) {
        int k = i >> 8, g = i & 255;
        ws[i] = g_WTe[k * GG + g];
    }
    // register half: column tid+256
    float w1r[KK];
#pragma unroll
    for (int k = 0; k < KK; ++k) w1r[k] = g_WTe[k * GG + 256 + tid];

    for (int i = tid; i < KK * BT; i += NTHR) xh[i] = 0.0f;
    if (tid < BT * EIN) {
        int r = tid / EIN, k = tid - r * EIN;
        xh[k * BT + r] = g_fe[(size_t)(b0r + r) * LL * EIN + k];
    }
    if (tid < 128) {
        hw[tid]       = Wm[tid];
        hw[128 + tid] = Wsw[tid];
#pragma unroll
        for (int d = 0; d < 4; ++d) hw[256 + d * 128 + tid] = Wv[d * 128 + tid];
    }
    if (tid == 0) {
        hw[768] = bm[0]; hw[769] = bs[0];
        hw[770] = bv[0]; hw[771] = bv[1]; hw[772] = bv[2]; hw[773] = bv[3];
    }

    ull bias0 = pack2(b_e[tid]);
    ull bias1 = pack2(b_e[tid + 256]);

    float c0 = 0.f, c1 = 0.f, c2 = 0.f, c3 = 0.f;
    const int j    = tid & 127;          // cell element
    const int roff = (tid >> 7) << 2;    // rows 0-3 or 4-7
    const int lane = tid & 31, wrp = tid >> 5;

    // ---------------- fused encoder+decoder loop ----------------
#pragma unroll 1
    for (int t = 0; t < LL + DEC; ++t) {
        if (t == LL) {
            // swap to decoder weights (all prior ws reads completed before the
            // step-(LL-1) gates barrier; loop-top barrier orders the new writes)
            for (int i = tid; i < KK * W0N; i += NTHR) {
                int k = i >> 8, g = i & 255;
                ws[i] = g_WTd[k * GG + g];
            }
#pragma unroll
            for (int k = 0; k < KK; ++k) w1r[k] = g_WTd[k * GG + 256 + tid];
            bias0 = pack2(b_d[tid]);
            bias1 = pack2(b_d[tid + 256]);
        }
        __syncthreads();                       // xh (+ws on swap) ready

        // ---- gate matmul: 2 columns x 8 batch rows, packed fp32x2 ----
        ull a00 = bias0, a01 = bias0, a02 = bias0, a03 = bias0;
        ull a10 = bias1, a11 = bias1, a12 = bias1, a13 = bias1;
        {
            const float* wp = ws + tid;
#pragma unroll
            for (int k = 0; k < KK; ++k) {
                ull w0d = pack2(wp[k * W0N]);
                ull w1d = pack2(w1r[k]);
                ulonglong2 xa = *reinterpret_cast<const ulonglong2*>(xh + k * BT);
                ulonglong2 xb = *reinterpret_cast<const ulonglong2*>(xh + k * BT + 4);
                a00 = ffma2(w0d, xa.x, a00);  a01 = ffma2(w0d, xa.y, a01);
                a02 = ffma2(w0d, xb.x, a02);  a03 = ffma2(w0d, xb.y, a03);
                a10 = ffma2(w1d, xa.x, a10);  a11 = ffma2(w1d, xa.y, a11);
                a12 = ffma2(w1d, xb.x, a12);  a13 = ffma2(w1d, xb.y, a13);
            }
        }
        *reinterpret_cast<ulonglong2*>(gates + tid * BT)             = make_ulonglong2(a00, a01);
        *reinterpret_cast<ulonglong2*>(gates + tid * BT + 4)         = make_ulonglong2(a02, a03);
        *reinterpret_cast<ulonglong2*>(gates + (tid + 256) * BT)     = make_ulonglong2(a10, a11);
        *reinterpret_cast<ulonglong2*>(gates + (tid + 256) * BT + 4) = make_ulonglong2(a12, a13);

        // ---- prefetch next step's input features (latency hidden by matmul tail) ----
        float pf = 0.0f; bool havepf = false; int pr = 0, pk = 0;
        if (t < LL - 1) {
            if (tid < BT * EIN) {
                havepf = true; pr = tid / EIN; pk = tid - pr * EIN;
                pf = g_fe[(size_t)(b0r + pr) * LL * EIN + (size_t)(t + 1) * EIN + pk];
            }
        } else if (t >= LL && t < LL + DEC - 1) {
            int td = t - LL;
            if (tid < BT * 17) {
                havepf = true; pr = tid / 17; pk = tid - pr * 17;
                pf = g_fd[((b0r + pr) * DEC + td) * 17 + pk];
            }
        }
        __syncthreads();                       // gates complete

        // ---- LSTM cell: 256 threads, 4 batch rows each ----
        {
            const float4 iv = *reinterpret_cast<const float4*>(gates + j * BT + roff);
            const float4 fv = *reinterpret_cast<const float4*>(gates + (128 + j) * BT + roff);
            const float4 gv = *reinterpret_cast<const float4*>(gates + (256 + j) * BT + roff);
            const float4 ov = *reinterpret_cast<const float4*>(gates + (384 + j) * BT + roff);
            c0 = sigf(fv.x) * c0 + sigf(iv.x) * tanh_f(gv.x);
            c1 = sigf(fv.y) * c1 + sigf(iv.y) * tanh_f(gv.y);
            c2 = sigf(fv.z) * c2 + sigf(iv.z) * tanh_f(gv.z);
            c3 = sigf(fv.w) * c3 + sigf(iv.w) * tanh_f(gv.w);
            float4 hv;
            hv.x = sigf(ov.x) * tanh_f(c0);
            hv.y = sigf(ov.y) * tanh_f(c1);
            hv.z = sigf(ov.z) * tanh_f(c2);
            hv.w = sigf(ov.w) * tanh_f(c3);
            *reinterpret_cast<float4*>(xh + (EIN + j) * BT + roff) = hv;
        }

        // ---- decoder heads ----
        if (t >= LL) {
            int td = t - LL;
            __syncthreads();                   // h complete
            int r = wrp;                       // 8 warps -> 8 batch rows
            float hm = 0.f, hs = 0.f, hv0 = 0.f, hv1 = 0.f, hv2 = 0.f, hv3 = 0.f;
#pragma unroll
            for (int q = 0; q < 4; ++q) {
                int jj = lane + q * 32;
                float h = xh[(EIN + jj) * BT + r];
                hm  = fmaf(h, hw[jj], hm);
                hs  = fmaf(h, hw[128 + jj], hs);
                hv0 = fmaf(h, hw[256 + jj], hv0);
                hv1 = fmaf(h, hw[384 + jj], hv1);
                hv2 = fmaf(h, hw[512 + jj], hv2);
                hv3 = fmaf(h, hw[640 + jj], hv3);
            }
#pragma unroll
            for (int off = 16; off; off >>= 1) {
                hm  += __shfl_xor_sync(0xffffffffu, hm,  off);
                hs  += __shfl_xor_sync(0xffffffffu, hs,  off);
                hv0 += __shfl_xor_sync(0xffffffffu, hv0, off);
                hv1 += __shfl_xor_sync(0xffffffffu, hv1, off);
                hv2 += __shfl_xor_sync(0xffffffffu, hv2, off);
                hv3 += __shfl_xor_sync(0xffffffffu, hv3, off);
            }
            if (lane == 0) {
                float mu = hm + hw[768];
                float sp = hs + hw[769];
                float stdv = fmaxf(sp, 0.0f) + log1pf(__expf(-fabsf(sp)));
                int b = b0r + r;
                out[b * DEC + td] = mu;
                out[BB * DEC + b * DEC + td] = stdv;
                float* vo = out + 2 * BB * DEC + (b * DEC + td) * 4;
                vo[0] = hv0 + hw[770]; vo[1] = hv1 + hw[771];
                vo[2] = hv2 + hw[772]; vo[3] = hv3 + hw[773];
                xh[17 * BT + r] = mu;          // mu feedback -> x_prev
            }
        }
        if (havepf) xh[pk * BT + pr] = pf;     // next step's x features
    }
}

// ---------------- launch ----------------
extern "C" void kernel_launch(void* const* d_in, const int* in_sizes, int n_in,
                              void* d_out, int out_size) {
    const int*   cat_in   = (const int*)d_in[0];
    const float* cont_in  = (const float*)d_in[1];
    const float* X_in     = (const float*)d_in[2];
    const int*   cat_out  = (const int*)d_in[3];
    const float* cont_out = (const float*)d_in[4];
    const float* emb      = (const float*)d_in[5];
    const float* cw       = (const float*)d_in[6];
    const float* Wih_e    = (const float*)d_in[7];
    const float* Whh_e    = (const float*)d_in[8];
    const float* b_e      = (const float*)d_in[9];
    const float* Wih_d    = (const float*)d_in[10];
    const float* Whh_d    = (const float*)d_in[11];
    const float* b_d      = (const float*)d_in[12];
    const float* Wm       = (const float*)d_in[13];
    const float* bm       = (const float*)d_in[14];
    const float* Ws       = (const float*)d_in[15];
    const float* bs       = (const float*)d_in[16];
    const float* Wv       = (const float*)d_in[17];
    const float* bv       = (const float*)d_in[18];
    float* out = (float*)d_out;

    float *pWTe, *pWTd, *pfe, *pfd;
    cudaGetSymbolAddress((void**)&pWTe, g_WTe);
    cudaGetSymbolAddress((void**)&pWTd, g_WTd);
    cudaGetSymbolAddress((void**)&pfe,  g_fe);
    cudaGetSymbolAddress((void**)&pfd,  g_fd);

    prep_weights<<<(KK * GG + 255) / 256, 256>>>(Wih_e, Whh_e, pWTe);
    prep_weights<<<(KK * GG + 255) / 256, 256>>>(Wih_d, Whh_d, pWTd);
    size_t ne = (size_t)BB * LL * EIN;
    prep_fe<<<(unsigned)((ne + 255) / 256), 256>>>(cat_in, cont_in, X_in, emb, cw, pfe);
    prep_fd<<<(BB * DEC * 17 + 255) / 256, 256>>>(cat_out, cont_out, emb, cw, pfd);

    int smem_bytes = (KK * W0N + KK * BT + GG * BT + 774) * (int)sizeof(float);
    cudaFuncSetAttribute(model_kernel, cudaFuncAttributeMaxDynamicSharedMemorySize, smem_bytes);
    model_kernel<<<NCTA, NTHR, smem_bytes>>>(b_e, b_d, Wm, bm, Ws, bs, Wv, bv, out);
}

// round 5
// speedup vs baseline: 3.6472x; 1.5698x over previous
#include <cuda_runtime.h>
#include <cuda_fp16.h>
#include <cstdint>
#include <math.h>

// Problem constants
#define BB   1024
#define LL   2048
#define DEC  64
#define HH   128
#define GG   512         // 4*H gate rows
#define EINF 18          // encoder input features (16 emb + cont*w + x)
#define KPAD 160         // padded K: 18 x + 128 h + 14 zero -> 10 k-tiles of 16
#define NKT  10
#define BT   8           // batch rows per CTA (= mma N)
#define NCTA (BB/BT)     // 128
#define NTHR 256
#define XST  168         // xhT row stride in fp16 elems (bank-friendly padding)
#define GST  12          // gates row stride in floats (16B-align friendly)
#define LOSC 2048.0f     // Wlo scale (2^11)
#define LOIV (1.0f/2048.0f)
#define NFRAG 10240      // 8 warps * 4 mtiles * 10 ktiles * 32 lanes

// ---------------- persistent device scratch ----------------
__device__ uint4 g_Whf_e[NFRAG];   // enc W hi, mma-fragment order
__device__ uint4 g_Wlf_e[NFRAG];   // enc W lo (scaled), fragment order
__device__ uint4 g_Whf_d[NFRAG];   // dec
__device__ uint4 g_Wlf_d[NFRAG];
__device__ float g_fe[(size_t)BB * LL * EINF];
__device__ float g_fd[BB * DEC * 17];

// ---------------- smem byte layout ----------------
#define WLO_OFF   0                         // 163840 B : Wlo fragments
#define XHT_OFF   163840                    // 2688 B   : xh^T fp16 [8][168]
#define GATES_OFF 166528                    // 24576 B  : gates fp32 [512][12]
#define HBUF_OFF  191104                    // 4096 B   : h fp32 [128][8]
#define HW_OFF    195200                    // 3096 B   : head weights/biases
#define SMEM_TOTAL 198304

// ---------------- mma wrapper ----------------
__device__ __forceinline__ void mma_f16(float* d, const uint4& a,
                                        uint32_t b0, uint32_t b1) {
    asm volatile(
        "mma.sync.aligned.m16n8k16.row.col.f32.f16.f16.f32 "
        "{%0,%1,%2,%3}, {%4,%5,%6,%7}, {%8,%9}, {%0,%1,%2,%3};"
        : "+f"(d[0]), "+f"(d[1]), "+f"(d[2]), "+f"(d[3])
        : "r"(a.x), "r"(a.y), "r"(a.z), "r"(a.w), "r"(b0), "r"(b1));
}

// ---------------- fast activations ----------------
__device__ __forceinline__ float sigf(float x) {
    return __fdividef(1.0f, 1.0f + __expf(-x));
}
__device__ __forceinline__ float tanh_f(float x) {
    float e = __expf(-2.0f * fabsf(x));
    float t = (1.0f - e) * __fdividef(1.0f, 1.0f + e);
    return copysignf(t, x);
}

// ---------------- prep kernels ----------------
__device__ __forceinline__ float getW(const float* Wih, const float* Whh,
                                      int R, int k) {
    if (k < 18)  return Wih[R * 18 + k];
    if (k < 146) return Whh[R * 128 + (k - 18)];
    return 0.0f;
}
__device__ __forceinline__ uint32_t packh2(float a, float b) {
    __half2 h = __floats2half2_rn(a, b);   // low = a
    return *reinterpret_cast<uint32_t*>(&h);
}

__global__ void prep_Wfrag(const float* __restrict__ Wih,
                           const float* __restrict__ Whh,
                           uint4* __restrict__ hi_out,
                           uint4* __restrict__ lo_out) {
    int idx = blockIdx.x * blockDim.x + threadIdx.x;
    if (idx >= NFRAG) return;
    int frag = idx >> 5, lane = idx & 31;
    int w = frag / 40, rem = frag - w * 40;
    int mt = rem / 10, kt = rem - mt * 10;
    int g = lane >> 2, t4 = lane & 3;
    int R0 = w * 64 + mt * 16 + g, R1 = R0 + 8;
    int kc = kt * 16 + 2 * t4;
    // fragment element order: a0={R0,kc..},a1={R1,kc..},a2={R0,kc+8..},a3={R1,kc+8..}
    float v[8];
    v[0] = getW(Wih, Whh, R0, kc);     v[1] = getW(Wih, Whh, R0, kc + 1);
    v[2] = getW(Wih, Whh, R1, kc);     v[3] = getW(Wih, Whh, R1, kc + 1);
    v[4] = getW(Wih, Whh, R0, kc + 8); v[5] = getW(Wih, Whh, R0, kc + 9);
    v[6] = getW(Wih, Whh, R1, kc + 8); v[7] = getW(Wih, Whh, R1, kc + 9);
    float hi[8], lo[8];
#pragma unroll
    for (int i = 0; i < 8; ++i) {
        __half h = __float2half_rn(v[i]);
        hi[i] = __half2float(h);
        lo[i] = (v[i] - hi[i]) * LOSC;
    }
    hi_out[idx] = make_uint4(packh2(hi[0], hi[1]), packh2(hi[2], hi[3]),
                             packh2(hi[4], hi[5]), packh2(hi[6], hi[7]));
    lo_out[idx] = make_uint4(packh2(lo[0], lo[1]), packh2(lo[2], lo[3]),
                             packh2(lo[4], lo[5]), packh2(lo[6], lo[7]));
}

__global__ void prep_fe(const int* __restrict__ cat, const float* __restrict__ cont,
                        const float* __restrict__ X, const float* __restrict__ emb,
                        const float* __restrict__ cw, float* __restrict__ out) {
    size_t idx = (size_t)blockIdx.x * blockDim.x + threadIdx.x;
    if (idx >= (size_t)BB * LL * EINF) return;
    size_t bl = idx / EINF;
    int j = (int)(idx - bl * EINF);
    float v;
    if (j < 16)       v = emb[cat[bl] * 16 + j];
    else if (j == 16) v = cont[bl] * cw[0];
    else              v = X[bl];
    out[idx] = v;
}

__global__ void prep_fd(const int* __restrict__ cat, const float* __restrict__ cont,
                        const float* __restrict__ emb, const float* __restrict__ cw,
                        float* __restrict__ out) {
    int idx = blockIdx.x * blockDim.x + threadIdx.x;
    if (idx >= BB * DEC * 17) return;
    int bl = idx / 17, j = idx - bl * 17;
    out[idx] = (j < 16) ? emb[cat[bl] * 16 + j] : cont[bl] * cw[0];
}

// ---------------- main persistent kernel ----------------
__global__ void __launch_bounds__(NTHR, 1)
model_kernel(const float* __restrict__ b_e, const float* __restrict__ b_d,
             const float* __restrict__ Wm, const float* __restrict__ bm,
             const float* __restrict__ Wsw, const float* __restrict__ bs,
             const float* __restrict__ Wv, const float* __restrict__ bv,
             float* __restrict__ out) {
    extern __shared__ char smem[];
    uint4*  wloS  = reinterpret_cast<uint4*>(smem + WLO_OFF);
    __half* xh16  = reinterpret_cast<__half*>(smem + XHT_OFF);
    float*  gates = reinterpret_cast<float*>(smem + GATES_OFF);
    float*  hbuf  = reinterpret_cast<float*>(smem + HBUF_OFF);
    float*  hw    = reinterpret_cast<float*>(smem + HW_OFF);

    const int tid = threadIdx.x;
    const int b0r = blockIdx.x * BT;
    const int w = tid >> 5, lane = tid & 31;
    const int g = lane >> 2, t4 = lane & 3;
    const int j = tid & 127;           // cell element
    const int coff = (tid >> 7) * 4;   // batch cols 0-3 or 4-7
    const int wrp = tid >> 5;

    // ---- load encoder Whi into registers (fragment order) ----
    uint4 Wh[40];
    {
        const uint4* src = g_Whf_e + (size_t)w * 40 * 32 + lane;
#pragma unroll
        for (int i = 0; i < 40; ++i) Wh[i] = src[i * 32];
    }
    // Wlo -> smem
    for (int i = tid; i < NFRAG; i += NTHR) wloS[i] = g_Wlf_e[i];

    // biases for this thread's gate rows
    float bl4[4], bh4[4];
#pragma unroll
    for (int mt = 0; mt < 4; ++mt) {
        bl4[mt] = b_e[w * 64 + mt * 16 + g];
        bh4[mt] = b_e[w * 64 + mt * 16 + g + 8];
    }

    // zero xh tile (covers K padding cols permanently)
    for (int i = tid; i < (BT * XST) / 2; i += NTHR)
        reinterpret_cast<uint32_t*>(xh16)[i] = 0;

    // head weights
    if (tid < 128) {
        hw[tid]       = Wm[tid];
        hw[128 + tid] = Wsw[tid];
#pragma unroll
        for (int d = 0; d < 4; ++d) hw[256 + d * 128 + tid] = Wv[d * 128 + tid];
    }
    if (tid == 0) {
        hw[768] = bm[0]; hw[769] = bs[0];
        hw[770] = bv[0]; hw[771] = bv[1]; hw[772] = bv[2]; hw[773] = bv[3];
    }
    __syncthreads();
    // initial x features (t=0)
    if (tid < BT * EINF) {
        int pr = tid / EINF, pk = tid - pr * EINF;
        xh16[pr * XST + pk] =
            __float2half(g_fe[(size_t)(b0r + pr) * (LL * EINF) + pk]);
    }

    float c[4] = {0.f, 0.f, 0.f, 0.f};
    const uint4* wloT = wloS + (size_t)w * 40 * 32 + lane;  // this thread's lo frags
    const __half* xp = xh16 + g * XST;                      // B col n = g

#pragma unroll 1
    for (int t = 0; t < LL + DEC; ++t) {
        if (t == LL) {
            // swap to decoder weights (all Wlo reads done before prior sync)
            const uint4* src = g_Whf_d + (size_t)w * 40 * 32 + lane;
#pragma unroll
            for (int i = 0; i < 40; ++i) Wh[i] = src[i * 32];
            for (int i = tid; i < NFRAG; i += NTHR) wloS[i] = g_Wlf_d[i];
#pragma unroll
            for (int mt = 0; mt < 4; ++mt) {
                bl4[mt] = b_d[w * 64 + mt * 16 + g];
                bh4[mt] = b_d[w * 64 + mt * 16 + g + 8];
            }
        }
        __syncthreads();                      // B tile (+Wlo on swap) ready

        // ---- load B fragments (conflict-free LDS.32) ----
        uint32_t Bf0[NKT], Bf1[NKT];
#pragma unroll
        for (int kt = 0; kt < NKT; ++kt) {
            Bf0[kt] = *reinterpret_cast<const uint32_t*>(xp + kt * 16 + 2 * t4);
            Bf1[kt] = *reinterpret_cast<const uint32_t*>(xp + kt * 16 + 2 * t4 + 8);
        }

        // ---- gate GEMM: 2 halves x 2 mtiles, hi + scaled-lo chains ----
#pragma unroll
        for (int half = 0; half < 2; ++half) {
            float dh[2][4], dl[2][4];
#pragma unroll
            for (int m2 = 0; m2 < 2; ++m2) {
                int mt = half * 2 + m2;
                dh[m2][0] = bl4[mt]; dh[m2][1] = bl4[mt];
                dh[m2][2] = bh4[mt]; dh[m2][3] = bh4[mt];
                dl[m2][0] = 0.f; dl[m2][1] = 0.f; dl[m2][2] = 0.f; dl[m2][3] = 0.f;
            }
#pragma unroll
            for (int kt = 0; kt < NKT; ++kt) {
#pragma unroll
                for (int m2 = 0; m2 < 2; ++m2) {
                    int mt = half * 2 + m2;
                    mma_f16(dh[m2], Wh[mt * 10 + kt], Bf0[kt], Bf1[kt]);
                    uint4 L = wloT[(mt * 10 + kt) * 32];
                    mma_f16(dl[m2], L, Bf0[kt], Bf1[kt]);
                }
            }
#pragma unroll
            for (int m2 = 0; m2 < 2; ++m2) {
                int mt = half * 2 + m2;
                int R0 = w * 64 + mt * 16 + g;
                float g0 = dh[m2][0] + dl[m2][0] * LOIV;
                float g1 = dh[m2][1] + dl[m2][1] * LOIV;
                float g2 = dh[m2][2] + dl[m2][2] * LOIV;
                float g3 = dh[m2][3] + dl[m2][3] * LOIV;
                *reinterpret_cast<float2*>(gates + R0 * GST + 2 * t4) =
                    make_float2(g0, g1);
                *reinterpret_cast<float2*>(gates + (R0 + 8) * GST + 2 * t4) =
                    make_float2(g2, g3);
            }
        }

        // ---- prefetch next step's features into registers ----
        float pf = 0.0f; bool havepf = false; int pr = 0, pk = 0;
        if (t < LL - 1) {
            if (tid < BT * EINF) {
                havepf = true; pr = tid / EINF; pk = tid - pr * EINF;
                pf = g_fe[(size_t)(b0r + pr) * (LL * EINF) + (size_t)(t + 1) * EINF + pk];
            }
        } else if (t >= LL && t < LL + DEC - 1) {
            int td = t - LL;
            if (tid < BT * 17) {
                havepf = true; pr = tid / 17; pk = tid - pr * 17;
                pf = g_fd[((b0r + pr) * DEC + td) * 17 + pk];
            }
        }
        __syncthreads();                      // gates ready; all B reads done

        // ---- LSTM cell: thread j, 4 batch cols ----
        const float4 iv = *reinterpret_cast<const float4*>(gates + j * GST + coff);
        const float4 fv = *reinterpret_cast<const float4*>(gates + (128 + j) * GST + coff);
        const float4 gv = *reinterpret_cast<const float4*>(gates + (256 + j) * GST + coff);
        const float4 ov = *reinterpret_cast<const float4*>(gates + (384 + j) * GST + coff);
        float h[4];
        c[0] = sigf(fv.x) * c[0] + sigf(iv.x) * tanh_f(gv.x);
        c[1] = sigf(fv.y) * c[1] + sigf(iv.y) * tanh_f(gv.y);
        c[2] = sigf(fv.z) * c[2] + sigf(iv.z) * tanh_f(gv.z);
        c[3] = sigf(fv.w) * c[3] + sigf(iv.w) * tanh_f(gv.w);
        h[0] = sigf(ov.x) * tanh_f(c[0]);
        h[1] = sigf(ov.y) * tanh_f(c[1]);
        h[2] = sigf(ov.z) * tanh_f(c[2]);
        h[3] = sigf(ov.w) * tanh_f(c[3]);
#pragma unroll
        for (int q = 0; q < 4; ++q)
            xh16[(coff + q) * XST + 18 + j] = __float2half(h[q]);

        // ---- decoder heads ----
        if (t >= LL) {
            int td = t - LL;
#pragma unroll
            for (int q = 0; q < 4; ++q) hbuf[j * BT + coff + q] = h[q];
            __syncthreads();                  // h complete for heads
            int r = wrp;                      // 8 warps -> 8 batch rows
            float hm = 0.f, hs = 0.f, hv0 = 0.f, hv1 = 0.f, hv2 = 0.f, hv3 = 0.f;
#pragma unroll
            for (int q4 = 0; q4 < 4; ++q4) {
                int jj = lane + q4 * 32;
                float hh = hbuf[jj * BT + r];
                hm  = fmaf(hh, hw[jj], hm);
                hs  = fmaf(hh, hw[128 + jj], hs);
                hv0 = fmaf(hh, hw[256 + jj], hv0);
                hv1 = fmaf(hh, hw[384 + jj], hv1);
                hv2 = fmaf(hh, hw[512 + jj], hv2);
                hv3 = fmaf(hh, hw[640 + jj], hv3);
            }
#pragma unroll
            for (int off = 16; off; off >>= 1) {
                hm  += __shfl_xor_sync(0xffffffffu, hm,  off);
                hs  += __shfl_xor_sync(0xffffffffu, hs,  off);
                hv0 += __shfl_xor_sync(0xffffffffu, hv0, off);
                hv1 += __shfl_xor_sync(0xffffffffu, hv1, off);
                hv2 += __shfl_xor_sync(0xffffffffu, hv2, off);
                hv3 += __shfl_xor_sync(0xffffffffu, hv3, off);
            }
            if (lane == 0) {
                float mu = hm + hw[768];
                float sp = hs + hw[769];
                float stdv = fmaxf(sp, 0.0f) + log1pf(__expf(-fabsf(sp)));
                int b = b0r + r;
                out[b * DEC + td] = mu;
                out[BB * DEC + b * DEC + td] = stdv;
                float* vo = out + 2 * BB * DEC + (b * DEC + td) * 4;
                vo[0] = hv0 + hw[770]; vo[1] = hv1 + hw[771];
                vo[2] = hv2 + hw[772]; vo[3] = hv3 + hw[773];
                xh16[r * XST + 17] = __float2half(mu);   // mu feedback -> x_prev
            }
        }
        if (havepf) xh16[pr * XST + pk] = __float2half(pf);
    }
}

// ---------------- launch ----------------
extern "C" void kernel_launch(void* const* d_in, const int* in_sizes, int n_in,
                              void* d_out, int out_size) {
    const int*   cat_in   = (const int*)d_in[0];
    const float* cont_in  = (const float*)d_in[1];
    const float* X_in     = (const float*)d_in[2];
    const int*   cat_out  = (const int*)d_in[3];
    const float* cont_out = (const float*)d_in[4];
    const float* emb      = (const float*)d_in[5];
    const float* cw       = (const float*)d_in[6];
    const float* Wih_e    = (const float*)d_in[7];
    const float* Whh_e    = (const float*)d_in[8];
    const float* b_e      = (const float*)d_in[9];
    const float* Wih_d    = (const float*)d_in[10];
    const float* Whh_d    = (const float*)d_in[11];
    const float* b_d      = (const float*)d_in[12];
    const float* Wm       = (const float*)d_in[13];
    const float* bm       = (const float*)d_in[14];
    const float* Ws       = (const float*)d_in[15];
    const float* bs       = (const float*)d_in[16];
    const float* Wv       = (const float*)d_in[17];
    const float* bv       = (const float*)d_in[18];
    float* out = (float*)d_out;

    uint4 *pWhe, *pWle, *pWhd, *pWld;
    float *pfe, *pfd;
    cudaGetSymbolAddress((void**)&pWhe, g_Whf_e);
    cudaGetSymbolAddress((void**)&pWle, g_Wlf_e);
    cudaGetSymbolAddress((void**)&pWhd, g_Whf_d);
    cudaGetSymbolAddress((void**)&pWld, g_Wlf_d);
    cudaGetSymbolAddress((void**)&pfe,  g_fe);
    cudaGetSymbolAddress((void**)&pfd,  g_fd);

    prep_Wfrag<<<(NFRAG + 255) / 256, 256>>>(Wih_e, Whh_e, pWhe, pWle);
    prep_Wfrag<<<(NFRAG + 255) / 256, 256>>>(Wih_d, Whh_d, pWhd, pWld);
    size_t ne = (size_t)BB * LL * EINF;
    prep_fe<<<(unsigned)((ne + 255) / 256), 256>>>(cat_in, cont_in, X_in, emb, cw, pfe);
    prep_fd<<<(BB * DEC * 17 + 255) / 256, 256>>>(cat_out, cont_out, emb, cw, pfd);

    cudaFuncSetAttribute(model_kernel, cudaFuncAttributeMaxDynamicSharedMemorySize,
                         SMEM_TOTAL);
    model_kernel<<<NCTA, NTHR, SMEM_TOTAL>>>(b_e, b_d, Wm, bm, Ws, bs, Wv, bv, out);
}

// round 6
// speedup vs baseline: 7.9097x; 2.1687x over previous
#include <cuda_runtime.h>
#include <cuda_fp16.h>
#include <cstdint>
#include <math.h>

// Problem constants
#define BB   1024
#define LL   2048
#define DEC  64
#define HH   128
#define GG   512         // 4*H gate rows
#define EINF 18          // encoder input features (16 emb + cont*w + x)
#define KPAD 160         // padded K: 18 x + 128 h + 14 zero -> 10 k-tiles of 16
#define NKT  10
#define BT   8           // batch rows per CTA (= mma N)
#define NCTA (BB/BT)     // 128
#define NTHR 256
#define XST  168         // xhT row stride in fp16 elems (bank-friendly padding)
#define GST  12          // gates row stride in floats (16B-align friendly)
#define NFRAG 10240      // 8 warps * 4 mtiles * 10 ktiles * 32 lanes

// ---------------- persistent device scratch ----------------
__device__ uint4 g_Whf_e[NFRAG];   // enc W fp16, mma-fragment order
__device__ uint4 g_Whf_d[NFRAG];   // dec
__device__ float g_fe[(size_t)BB * LL * EINF];
__device__ float g_fd[BB * DEC * 17];

// ---------------- smem byte layout ----------------
#define XHT_OFF   0                         // 2688 B   : xh^T fp16 [8][168]
#define GATES_OFF 2688                      // 24576 B  : gates fp32 [512][12]
#define HBUF_OFF  27264                     // 4096 B   : h fp32 [128][8]
#define HW_OFF    31360                     // 3096 B   : head weights/biases
#define SMEM_TOTAL 34560

// ---------------- mma wrapper ----------------
__device__ __forceinline__ void mma_f16(float* d, const uint4& a,
                                        uint32_t b0, uint32_t b1) {
    asm volatile(
        "mma.sync.aligned.m16n8k16.row.col.f32.f16.f16.f32 "
        "{%0,%1,%2,%3}, {%4,%5,%6,%7}, {%8,%9}, {%0,%1,%2,%3};"
        : "+f"(d[0]), "+f"(d[1]), "+f"(d[2]), "+f"(d[3])
        : "r"(a.x), "r"(a.y), "r"(a.z), "r"(a.w), "r"(b0), "r"(b1));
}

// ---------------- fast activations ----------------
__device__ __forceinline__ float sigf(float x) {
    return __fdividef(1.0f, 1.0f + __expf(-x));
}
__device__ __forceinline__ float tanh_f(float x) {
    float e = __expf(-2.0f * fabsf(x));
    float t = (1.0f - e) * __fdividef(1.0f, 1.0f + e);
    return copysignf(t, x);
}

// ---------------- prep kernels ----------------
__device__ __forceinline__ float getW(const float* Wih, const float* Whh,
                                      int R, int k) {
    if (k < 18)  return Wih[R * 18 + k];
    if (k < 146) return Whh[R * 128 + (k - 18)];
    return 0.0f;
}
__device__ __forceinline__ uint32_t packh2(float a, float b) {
    __half2 h = __floats2half2_rn(a, b);   // low = a
    return *reinterpret_cast<uint32_t*>(&h);
}

__global__ void prep_Wfrag(const float* __restrict__ Wih,
                           const float* __restrict__ Whh,
                           uint4* __restrict__ w_out) {
    int idx = blockIdx.x * blockDim.x + threadIdx.x;
    if (idx >= NFRAG) return;
    int frag = idx >> 5, lane = idx & 31;
    int w = frag / 40, rem = frag - w * 40;
    int mt = rem / 10, kt = rem - mt * 10;
    int g = lane >> 2, t4 = lane & 3;
    int R0 = w * 64 + mt * 16 + g, R1 = R0 + 8;
    int kc = kt * 16 + 2 * t4;
    // fragment order: a0={R0,kc..},a1={R1,kc..},a2={R0,kc+8..},a3={R1,kc+8..}
    float v[8];
    v[0] = getW(Wih, Whh, R0, kc);     v[1] = getW(Wih, Whh, R0, kc + 1);
    v[2] = getW(Wih, Whh, R1, kc);     v[3] = getW(Wih, Whh, R1, kc + 1);
    v[4] = getW(Wih, Whh, R0, kc + 8); v[5] = getW(Wih, Whh, R0, kc + 9);
    v[6] = getW(Wih, Whh, R1, kc + 8); v[7] = getW(Wih, Whh, R1, kc + 9);
    w_out[idx] = make_uint4(packh2(v[0], v[1]), packh2(v[2], v[3]),
                            packh2(v[4], v[5]), packh2(v[6], v[7]));
}

__global__ void prep_fe(const int* __restrict__ cat, const float* __restrict__ cont,
                        const float* __restrict__ X, const float* __restrict__ emb,
                        const float* __restrict__ cw, float* __restrict__ out) {
    size_t idx = (size_t)blockIdx.x * blockDim.x + threadIdx.x;
    if (idx >= (size_t)BB * LL * EINF) return;
    size_t bl = idx / EINF;
    int j = (int)(idx - bl * EINF);
    float v;
    if (j < 16)       v = emb[cat[bl] * 16 + j];
    else if (j == 16) v = cont[bl] * cw[0];
    else              v = X[bl];
    out[idx] = v;
}

__global__ void prep_fd(const int* __restrict__ cat, const float* __restrict__ cont,
                        const float* __restrict__ emb, const float* __restrict__ cw,
                        float* __restrict__ out) {
    int idx = blockIdx.x * blockDim.x + threadIdx.x;
    if (idx >= BB * DEC * 17) return;
    int bl = idx / 17, j = idx - bl * 17;
    out[idx] = (j < 16) ? emb[cat[bl] * 16 + j] : cont[bl] * cw[0];
}

// ---------------- main persistent kernel ----------------
__global__ void __launch_bounds__(NTHR, 1)
model_kernel(const float* __restrict__ b_e, const float* __restrict__ b_d,
             const float* __restrict__ Wm, const float* __restrict__ bm,
             const float* __restrict__ Wsw, const float* __restrict__ bs,
             const float* __restrict__ Wv, const float* __restrict__ bv,
             float* __restrict__ out) {
    extern __shared__ char smem[];
    __half* xh16  = reinterpret_cast<__half*>(smem + XHT_OFF);
    float*  gates = reinterpret_cast<float*>(smem + GATES_OFF);
    float*  hbuf  = reinterpret_cast<float*>(smem + HBUF_OFF);
    float*  hw    = reinterpret_cast<float*>(smem + HW_OFF);

    const int tid = threadIdx.x;
    const int b0r = blockIdx.x * BT;
    const int w = tid >> 5, lane = tid & 31;
    const int g = lane >> 2, t4 = lane & 3;
    const int j = tid & 127;           // cell element
    const int coff = (tid >> 7) * 4;   // batch cols 0-3 or 4-7
    const int wrp = tid >> 5;

    // ---- load encoder W into registers (fragment order) ----
    uint4 Wh[40];
    {
        const uint4* src = g_Whf_e + (size_t)w * 40 * 32 + lane;
#pragma unroll
        for (int i = 0; i < 40; ++i) Wh[i] = src[i * 32];
    }

    // biases for this thread's gate rows
    float bl4[4], bh4[4];
#pragma unroll
    for (int mt = 0; mt < 4; ++mt) {
        bl4[mt] = b_e[w * 64 + mt * 16 + g];
        bh4[mt] = b_e[w * 64 + mt * 16 + g + 8];
    }

    // zero xh tile (covers K padding cols permanently)
    for (int i = tid; i < (BT * XST) / 2; i += NTHR)
        reinterpret_cast<uint32_t*>(xh16)[i] = 0;

    // head weights
    if (tid < 128) {
        hw[tid]       = Wm[tid];
        hw[128 + tid] = Wsw[tid];
#pragma unroll
        for (int d = 0; d < 4; ++d) hw[256 + d * 128 + tid] = Wv[d * 128 + tid];
    }
    if (tid == 0) {
        hw[768] = bm[0]; hw[769] = bs[0];
        hw[770] = bv[0]; hw[771] = bv[1]; hw[772] = bv[2]; hw[773] = bv[3];
    }
    __syncthreads();
    // initial x features (t=0)
    if (tid < BT * EINF) {
        int pr = tid / EINF, pk = tid - pr * EINF;
        xh16[pr * XST + pk] =
            __float2half(g_fe[(size_t)(b0r + pr) * (LL * EINF) + pk]);
    }

    float c[4] = {0.f, 0.f, 0.f, 0.f};
    const __half* xp = xh16 + g * XST;   // B col n = g

#pragma unroll 1
    for (int t = 0; t < LL + DEC; ++t) {
        if (t == LL) {
            // swap to decoder weights
            const uint4* src = g_Whf_d + (size_t)w * 40 * 32 + lane;
#pragma unroll
            for (int i = 0; i < 40; ++i) Wh[i] = src[i * 32];
#pragma unroll
            for (int mt = 0; mt < 4; ++mt) {
                bl4[mt] = b_d[w * 64 + mt * 16 + g];
                bh4[mt] = b_d[w * 64 + mt * 16 + g + 8];
            }
        }
        __syncthreads();                      // B tile ready

        // ---- load B fragments ----
        uint32_t Bf0[NKT], Bf1[NKT];
#pragma unroll
        for (int kt = 0; kt < NKT; ++kt) {
            Bf0[kt] = *reinterpret_cast<const uint32_t*>(xp + kt * 16 + 2 * t4);
            Bf1[kt] = *reinterpret_cast<const uint32_t*>(xp + kt * 16 + 2 * t4 + 8);
        }

        // ---- gate GEMM: 4 mtiles, 4 independent accumulator chains ----
        float d0[4], d1[4], d2[4], d3[4];
        d0[0] = bl4[0]; d0[1] = bl4[0]; d0[2] = bh4[0]; d0[3] = bh4[0];
        d1[0] = bl4[1]; d1[1] = bl4[1]; d1[2] = bh4[1]; d1[3] = bh4[1];
        d2[0] = bl4[2]; d2[1] = bl4[2]; d2[2] = bh4[2]; d2[3] = bh4[2];
        d3[0] = bl4[3]; d3[1] = bl4[3]; d3[2] = bh4[3]; d3[3] = bh4[3];
#pragma unroll
        for (int kt = 0; kt < NKT; ++kt) {
            mma_f16(d0, Wh[0 * 10 + kt], Bf0[kt], Bf1[kt]);
            mma_f16(d1, Wh[1 * 10 + kt], Bf0[kt], Bf1[kt]);
            mma_f16(d2, Wh[2 * 10 + kt], Bf0[kt], Bf1[kt]);
            mma_f16(d3, Wh[3 * 10 + kt], Bf0[kt], Bf1[kt]);
        }
        {
            int R0 = w * 64 + g;
            *reinterpret_cast<float2*>(gates + (R0     ) * GST + 2 * t4) = make_float2(d0[0], d0[1]);
            *reinterpret_cast<float2*>(gates + (R0 +  8) * GST + 2 * t4) = make_float2(d0[2], d0[3]);
            *reinterpret_cast<float2*>(gates + (R0 + 16) * GST + 2 * t4) = make_float2(d1[0], d1[1]);
            *reinterpret_cast<float2*>(gates + (R0 + 24) * GST + 2 * t4) = make_float2(d1[2], d1[3]);
            *reinterpret_cast<float2*>(gates + (R0 + 32) * GST + 2 * t4) = make_float2(d2[0], d2[1]);
            *reinterpret_cast<float2*>(gates + (R0 + 40) * GST + 2 * t4) = make_float2(d2[2], d2[3]);
            *reinterpret_cast<float2*>(gates + (R0 + 48) * GST + 2 * t4) = make_float2(d3[0], d3[1]);
            *reinterpret_cast<float2*>(gates + (R0 + 56) * GST + 2 * t4) = make_float2(d3[2], d3[3]);
        }

        // ---- prefetch next step's features into registers ----
        float pf = 0.0f; bool havepf = false; int pr = 0, pk = 0;
        if (t < LL - 1) {
            if (tid < BT * EINF) {
                havepf = true; pr = tid / EINF; pk = tid - pr * EINF;
                pf = g_fe[(size_t)(b0r + pr) * (LL * EINF) + (size_t)(t + 1) * EINF + pk];
            }
        } else if (t >= LL && t < LL + DEC - 1) {
            int td = t - LL;
            if (tid < BT * 17) {
                havepf = true; pr = tid / 17; pk = tid - pr * 17;
                pf = g_fd[((b0r + pr) * DEC + td) * 17 + pk];
            }
        }
        __syncthreads();                      // gates ready; all B reads done

        // ---- LSTM cell: thread j, 4 batch cols ----
        const float4 iv = *reinterpret_cast<const float4*>(gates + j * GST + coff);
        const float4 fv = *reinterpret_cast<const float4*>(gates + (128 + j) * GST + coff);
        const float4 gv = *reinterpret_cast<const float4*>(gates + (256 + j) * GST + coff);
        const float4 ov = *reinterpret_cast<const float4*>(gates + (384 + j) * GST + coff);
        float h[4];
        c[0] = sigf(fv.x) * c[0] + sigf(iv.x) * tanh_f(gv.x);
        c[1] = sigf(fv.y) * c[1] + sigf(iv.y) * tanh_f(gv.y);
        c[2] = sigf(fv.z) * c[2] + sigf(iv.z) * tanh_f(gv.z);
        c[3] = sigf(fv.w) * c[3] + sigf(iv.w) * tanh_f(gv.w);
        h[0] = sigf(ov.x) * tanh_f(c[0]);
        h[1] = sigf(ov.y) * tanh_f(c[1]);
        h[2] = sigf(ov.z) * tanh_f(c[2]);
        h[3] = sigf(ov.w) * tanh_f(c[3]);
#pragma unroll
        for (int q = 0; q < 4; ++q)
            xh16[(coff + q) * XST + 18 + j] = __float2half(h[q]);

        // ---- decoder heads ----
        if (t >= LL) {
            int td = t - LL;
#pragma unroll
            for (int q = 0; q < 4; ++q) hbuf[j * BT + coff + q] = h[q];
            __syncthreads();                  // h complete for heads
            int r = wrp;                      // 8 warps -> 8 batch rows
            float hm = 0.f, hs = 0.f, hv0 = 0.f, hv1 = 0.f, hv2 = 0.f, hv3 = 0.f;
#pragma unroll
            for (int q4 = 0; q4 < 4; ++q4) {
                int jj = lane + q4 * 32;
                float hh = hbuf[jj * BT + r];
                hm  = fmaf(hh, hw[jj], hm);
                hs  = fmaf(hh, hw[128 + jj], hs);
                hv0 = fmaf(hh, hw[256 + jj], hv0);
                hv1 = fmaf(hh, hw[384 + jj], hv1);
                hv2 = fmaf(hh, hw[512 + jj], hv2);
                hv3 = fmaf(hh, hw[640 + jj], hv3);
            }
#pragma unroll
            for (int off = 16; off; off >>= 1) {
                hm  += __shfl_xor_sync(0xffffffffu, hm,  off);
                hs  += __shfl_xor_sync(0xffffffffu, hs,  off);
                hv0 += __shfl_xor_sync(0xffffffffu, hv0, off);
                hv1 += __shfl_xor_sync(0xffffffffu, hv1, off);
                hv2 += __shfl_xor_sync(0xffffffffu, hv2, off);
                hv3 += __shfl_xor_sync(0xffffffffu, hv3, off);
            }
            if (lane == 0) {
                float mu = hm + hw[768];
                float sp = hs + hw[769];
                float stdv = fmaxf(sp, 0.0f) + log1pf(__expf(-fabsf(sp)));
                int b = b0r + r;
                out[b * DEC + td] = mu;
                out[BB * DEC + b * DEC + td] = stdv;
                float* vo = out + 2 * BB * DEC + (b * DEC + td) * 4;
                vo[0] = hv0 + hw[770]; vo[1] = hv1 + hw[771];
                vo[2] = hv2 + hw[772]; vo[3] = hv3 + hw[773];
                xh16[r * XST + 17] = __float2half(mu);   // mu feedback -> x_prev
            }
        }
        if (havepf) xh16[pr * XST + pk] = __float2half(pf);
    }
}

// ---------------- launch ----------------
extern "C" void kernel_launch(void* const* d_in, const int* in_sizes, int n_in,
                              void* d_out, int out_size) {
    const int*   cat_in   = (const int*)d_in[0];
    const float* cont_in  = (const float*)d_in[1];
    const float* X_in     = (const float*)d_in[2];
    const int*   cat_out  = (const int*)d_in[3];
    const float* cont_out = (const float*)d_in[4];
    const float* emb      = (const float*)d_in[5];
    const float* cw       = (const float*)d_in[6];
    const float* Wih_e    = (const float*)d_in[7];
    const float* Whh_e    = (const float*)d_in[8];
    const float* b_e      = (const float*)d_in[9];
    const float* Wih_d    = (const float*)d_in[10];
    const float* Whh_d    = (const float*)d_in[11];
    const float* b_d      = (const float*)d_in[12];
    const float* Wm       = (const float*)d_in[13];
    const float* bm       = (const float*)d_in[14];
    const float* Ws       = (const float*)d_in[15];
    const float* bs       = (const float*)d_in[16];
    const float* Wv       = (const float*)d_in[17];
    const float* bv       = (const float*)d_in[18];
    float* out = (float*)d_out;

    uint4 *pWhe, *pWhd;
    float *pfe, *pfd;
    cudaGetSymbolAddress((void**)&pWhe, g_Whf_e);
    cudaGetSymbolAddress((void**)&pWhd, g_Whf_d);
    cudaGetSymbolAddress((void**)&pfe,  g_fe);
    cudaGetSymbolAddress((void**)&pfd,  g_fd);

    prep_Wfrag<<<(NFRAG + 255) / 256, 256>>>(Wih_e, Whh_e, pWhe);
    prep_Wfrag<<<(NFRAG + 255) / 256, 256>>>(Wih_d, Whh_d, pWhd);
    size_t ne = (size_t)BB * LL * EINF;
    prep_fe<<<(unsigned)((ne + 255) / 256), 256>>>(cat_in, cont_in, X_in, emb, cw, pfe);
    prep_fd<<<(BB * DEC * 17 + 255) / 256, 256>>>(cat_out, cont_out, emb, cw, pfd);

    cudaFuncSetAttribute(model_kernel, cudaFuncAttributeMaxDynamicSharedMemorySize,
                         SMEM_TOTAL);
    model_kernel<<<NCTA, NTHR, SMEM_TOTAL>>>(b_e, b_d, Wm, bm, Ws, bs, Wv, bv, out);
}